// round 7
// baseline (speedup 1.0000x reference)
#include <cuda_runtime.h>
#include <cstdint>

#define Hh 512
#define Ww 512
#define Cc 32
#define Bb 4
#define Ss (Hh*Ww)

typedef unsigned long long ull;

__device__ __forceinline__ ull pack2(float a, float b) {
    ull r; asm("mov.b64 %0, {%1, %2};" : "=l"(r) : "f"(a), "f"(b)); return r;
}
__device__ __forceinline__ void unpack2(ull v, float& a, float& b) {
    asm("mov.b64 {%0, %1}, %2;" : "=f"(a), "=f"(b) : "l"(v));
}
__device__ __forceinline__ ull fma2(ull a, ull b, ull c) {
    ull d; asm("fma.rn.f32x2 %0, %1, %2, %3;" : "=l"(d) : "l"(a), "l"(b), "l"(c)); return d;
}

#define CG 8              // channels per staging group
#define TPITCH 36         // padded smem row pitch (floats)
#define FUSE_SMEM (CG * 34 * TPITCH * 4 + Cc * 9 * 8)   // 41472 B

// ---------------------------------------------------------------------------
// Fully fused deformable conv, R7.
//
// Phase A (offset conv; only channels 0,1 of the 18 are consumed downstream):
//   32x32 tile, channels staged to smem in groups of 8, thread = 2x2 px,
//   packed f32x2 accumulation. Identical math to the R4/R6 conv.
// Phase B (bilinear sampling): offsets stay in REGISTERS (no 16MB scratch
//   round-trip), sampling reads x straight from GLOBAL via the proven
//   L1-hit-rich path with full clamp+validity (exact jnp semantics, no
//   fast-path/fallback split).
//
// Why fused: the standalone conv kernel was stuck at ~95us across occupancy/
// LDS experiments — as a short barrier-phased kernel it never reaches steady
// state. Here each block's conv stalls overlap other blocks' sampling phases
// (512 independent LDGs each). smem stays 41.5KB dynamic (~3 blocks/SM), NOT
// the 226KB monolith that caused the R5 occupancy collapse.
// ---------------------------------------------------------------------------
__global__ __launch_bounds__(256) void fused_deform_kernel(
    const float* __restrict__ x,
    const float* __restrict__ w_off,
    const float* __restrict__ b_off,
    float* __restrict__ out)
{
    extern __shared__ float dsm[];
    float*  s_tile = dsm;                                // [CG][34*TPITCH]
    float2* s_w    = (float2*)(dsm + CG * 34 * TPITCH);  // [288]

    const int tid = threadIdx.x;
    const int tx = tid & 15;    // pixel cols 2tx, 2tx+1
    const int ty = tid >> 4;    // pixel rows 2ty, 2ty+1
    const int bx = blockIdx.x, by = blockIdx.y, bz = blockIdx.z;

    for (int i = tid; i < Cc * 9; i += 256)
        s_w[i] = make_float2(__ldg(w_off + i), __ldg(w_off + 288 + i));

    const int gx0 = bx * 32 - 1;
    const int gy0 = by * 32 - 1;
    const float* xb = x + (size_t)bz * Cc * Ss;

    const float b0v = __ldg(b_off + 0);
    const float b1v = __ldg(b_off + 1);

    // ===================== Phase A: offset conv =====================
    ull acc[4];
    const ull biasp = pack2(b0v, b1v);
#pragma unroll
    for (int i = 0; i < 4; i++) acc[i] = biasp;

    for (int g = 0; g < Cc / CG; g++) {
#pragma unroll
        for (int c8 = 0; c8 < CG; c8++) {
            const float* xc = xb + (size_t)(g * CG + c8) * Ss;
            float* buf = s_tile + c8 * (34 * TPITCH);
#pragma unroll
            for (int i = tid; i < 34 * 34; i += 256) {
                int r = i / 34;
                int q = i - r * 34;
                int gy = gy0 + r;
                int gx = gx0 + q;
                float v = 0.0f;
                if ((unsigned)gy < (unsigned)Hh && (unsigned)gx < (unsigned)Ww)
                    v = __ldg(xc + gy * Ww + gx);
                buf[r * TPITCH + q] = v;
            }
        }
        __syncthreads();

#pragma unroll
        for (int c8 = 0; c8 < CG; c8++) {
            const float* curp = s_tile + c8 * (34 * TPITCH);

            ull wk[9];
#pragma unroll
            for (int k = 0; k < 9; k++) {
                float2 t = s_w[(g * CG + c8) * 9 + k];
                wk[k] = pack2(t.x, t.y);
            }

            ull pv[4][4];
#pragma unroll
            for (int r = 0; r < 4; r++) {
                const float2* rp = reinterpret_cast<const float2*>(
                    curp + (2 * ty + r) * TPITCH + 2 * tx);
                float2 a = rp[0];
                float2 bq = rp[1];
                pv[r][0] = pack2(a.x, a.x);
                pv[r][1] = pack2(a.y, a.y);
                pv[r][2] = pack2(bq.x, bq.x);
                pv[r][3] = pack2(bq.y, bq.y);
            }

#pragma unroll
            for (int pr = 0; pr < 2; pr++) {
#pragma unroll
                for (int pc = 0; pc < 2; pc++) {
                    ull a = acc[pr * 2 + pc];
#pragma unroll
                    for (int ky = 0; ky < 3; ky++) {
#pragma unroll
                        for (int kx = 0; kx < 3; kx++) {
                            a = fma2(pv[pr + ky][pc + kx], wk[ky * 3 + kx], a);
                        }
                    }
                    acc[pr * 2 + pc] = a;
                }
            }
        }
        __syncthreads();
    }

    // ===================== Phase B: bilinear sampling =====================
    // Per-pixel corner indices + weights, full clamp+validity (jnp semantics).
    int   i00[4], i01[4], i10[4], i11[4];
    float w00[4], w01[4], w10[4], w11[4];

#pragma unroll
    for (int p = 0; p < 4; p++) {
        int pr = p >> 1, pc = p & 1;
        int px = bx * 32 + 2 * tx + pc;
        int py = by * 32 + 2 * ty + pr;
        float offx, offy;
        unpack2(acc[pr * 2 + pc], offx, offy);
        float ix = (float)px + offx;
        float iy = (float)py + offy;

        float x0f = floorf(ix);
        float y0f = floorf(iy);
        float wx1 = ix - x0f, wx0 = 1.0f - wx1;
        float wy1 = iy - y0f, wy0 = 1.0f - wy1;

        float fx0 = (x0f >= 0.0f && x0f <= 511.0f) ? 1.0f : 0.0f;
        float fx1 = (x0f >= -1.0f && x0f <= 510.0f) ? 1.0f : 0.0f;
        float fy0 = (y0f >= 0.0f && y0f <= 511.0f) ? 1.0f : 0.0f;
        float fy1 = (y0f >= -1.0f && y0f <= 510.0f) ? 1.0f : 0.0f;

        int ix0r = (int)x0f, iy0r = (int)y0f;
        int xi0 = max(0, min(511, ix0r));
        int xi1 = max(0, min(511, ix0r + 1));
        int yi0 = max(0, min(511, iy0r));
        int yi1 = max(0, min(511, iy0r + 1));

        w00[p] = wy0 * wx0 * (fy0 * fx0);
        w01[p] = wy0 * wx1 * (fy0 * fx1);
        w10[p] = wy1 * wx0 * (fy1 * fx0);
        w11[p] = wy1 * wx1 * (fy1 * fx1);

        i00[p] = yi0 * Ww + xi0;
        i01[p] = yi0 * Ww + xi1;
        i10[p] = yi1 * Ww + xi0;
        i11[p] = yi1 * Ww + xi1;
    }

    const size_t obase = (size_t)bz * Cc * Ss
                       + (size_t)(by * 32 + 2 * ty) * Ww + (bx * 32 + 2 * tx);
#pragma unroll 2
    for (int c = 0; c < Cc; c++) {
        const float* p = xb + (size_t)c * Ss;
        float v[4];
#pragma unroll
        for (int q = 0; q < 4; q++) {
            v[q] = w00[q] * __ldg(p + i00[q])
                 + w01[q] * __ldg(p + i01[q])
                 + w10[q] * __ldg(p + i10[q])
                 + w11[q] * __ldg(p + i11[q]);
        }
        float* op = out + obase + (size_t)c * Ss;
        __stcs(reinterpret_cast<float2*>(op),      make_float2(v[0], v[1]));
        __stcs(reinterpret_cast<float2*>(op + Ww), make_float2(v[2], v[3]));
    }
}

extern "C" void kernel_launch(void* const* d_in, const int* in_sizes, int n_in,
                              void* d_out, int out_size)
{
    const float* x     = (const float*)d_in[0];  // (4, 32, 512, 512)
    const float* w_off = (const float*)d_in[1];  // (18, 32, 3, 3)
    const float* b_off = (const float*)d_in[2];  // (18,)
    float* out = (float*)d_out;                  // (4, 32, 512, 512)

    (void)in_sizes; (void)n_in; (void)out_size;

    cudaFuncSetAttribute(fused_deform_kernel,
                         cudaFuncAttributeMaxDynamicSharedMemorySize, FUSE_SMEM);

    dim3 grid(Ww / 32, Hh / 32, Bb);
    fused_deform_kernel<<<grid, 256, FUSE_SMEM>>>(x, w_off, b_off, out);
}

// round 8
// speedup vs baseline: 1.2303x; 1.2303x over previous
#include <cuda_runtime.h>
#include <cstdint>

#define Hh 512
#define Ww 512
#define Cc 32
#define Bb 4
#define Ss (Hh*Ww)

// Scratch: per-pixel (off_x, off_y), 4*512*512*8B = 8 MB
__device__ float2 g_off_buf[Bb * Ss];

typedef unsigned long long ull;

__device__ __forceinline__ ull pack2(float a, float b) {
    ull r; asm("mov.b64 %0, {%1, %2};" : "=l"(r) : "f"(a), "f"(b)); return r;
}
__device__ __forceinline__ void unpack2(ull v, float& a, float& b) {
    asm("mov.b64 {%0, %1}, %2;" : "=f"(a), "=f"(b) : "l"(v));
}
__device__ __forceinline__ ull fma2(ull a, ull b, ull c) {
    ull d; asm("fma.rn.f32x2 %0, %1, %2, %3;" : "=l"(d) : "l"(a), "l"(b), "l"(c)); return d;
}

// ---------------------------------------------------------------------------
// Kernel 1: offset conv (only channels 0,1 of the 18 matter downstream).
//
// R8 redesign: BARRIER-FREE warp-strip conv. Every smem-staged variant sat at
// ~92us regardless of occupancy/vector width — the common factor was the
// stage->__syncthreads->compute phase structure. Here each warp owns a
// 128-wide x 4-tall strip: per channel it streams 6 input rows (aligned
// LDG.128 + 2 edge scalars per row) straight from global (L1/L2 give halo
// reuse) and rotates them into the 9-tap accumulation. No x staging, no
// barriers, 18 independent LDGs of MLP per channel iteration.
//
// Block = 64 threads (2 warps) covering 128x8; grid (4, 64, 4) = 1024 blocks.
// Accumulation packed (off_x, off_y) via fma.rn.f32x2.
// ---------------------------------------------------------------------------
__global__ __launch_bounds__(64) void conv_off_kernel(
    const float* __restrict__ x,
    const float* __restrict__ w_off,
    const float* __restrict__ b_off)
{
    __shared__ ull s_wk[Cc * 9];   // packed (w_ch0, w_ch1) per (c,k)

    const int tid  = threadIdx.x;
    const int wid  = tid >> 5;
    const int lane = tid & 31;

    for (int i = tid; i < Cc * 9; i += 64)
        s_wk[i] = pack2(__ldg(w_off + i), __ldg(w_off + 288 + i));
    __syncthreads();

    const int X0   = blockIdx.x * 128;
    const int ytop = blockIdx.y * 8 + wid * 4;   // out rows ytop..ytop+3
    const int bz   = blockIdx.z;
    const int cb   = X0 + 4 * lane;              // lane's first pixel column
    const float* xb = x + (size_t)bz * Cc * Ss;

    const ull biasp = pack2(__ldg(b_off + 0), __ldg(b_off + 1));
    ull acc[4][4];
#pragma unroll
    for (int r = 0; r < 4; r++)
#pragma unroll
        for (int p = 0; p < 4; p++) acc[r][p] = biasp;

    const bool has_left  = (cb > 0);
    const bool has_right = (cb + 4 < Ww);

    for (int c = 0; c < Cc; c++) {
        const float* xc = xb + (size_t)c * Ss;

        ull wk[9];
#pragma unroll
        for (int k = 0; k < 9; k++) wk[k] = s_wk[c * 9 + k];

#pragma unroll
        for (int j = 0; j < 6; j++) {           // input rows ytop-1 .. ytop+4
            int gy = ytop - 1 + j;
            float v0 = 0.f, v1 = 0.f, v2 = 0.f, v3 = 0.f, v4 = 0.f, v5 = 0.f;
            if ((unsigned)gy < (unsigned)Hh) {
                const float* rp = xc + gy * Ww + cb;
                float4 m = __ldg(reinterpret_cast<const float4*>(rp));
                v1 = m.x; v2 = m.y; v3 = m.z; v4 = m.w;
                if (has_left)  v0 = __ldg(rp - 1);
                if (has_right) v5 = __ldg(rp + 4);
            }
            ull pv[6];
            pv[0] = pack2(v0, v0); pv[1] = pack2(v1, v1);
            pv[2] = pack2(v2, v2); pv[3] = pack2(v3, v3);
            pv[4] = pack2(v4, v4); pv[5] = pack2(v5, v5);

            // input row gy feeds output row r = j - ky with weight row ky
#pragma unroll
            for (int ky = 0; ky < 3; ky++) {
                int r = j - ky;
                if (r >= 0 && r < 4) {          // compile-time (j,ky unrolled)
#pragma unroll
                    for (int p = 0; p < 4; p++) {
                        ull a = acc[r][p];
                        a = fma2(pv[p],     wk[ky * 3 + 0], a);
                        a = fma2(pv[p + 1], wk[ky * 3 + 1], a);
                        a = fma2(pv[p + 2], wk[ky * 3 + 2], a);
                        acc[r][p] = a;
                    }
                }
            }
        }
    }

    // store 4 rows x 4 px of (off_x, off_y): two coalesced STG.128 per row
#pragma unroll
    for (int r = 0; r < 4; r++) {
        int y = ytop + r;
        float2* op = g_off_buf + (size_t)bz * Ss + (size_t)y * Ww + cb;
        float ox0, oy0, ox1, oy1, ox2, oy2, ox3, oy3;
        unpack2(acc[r][0], ox0, oy0);
        unpack2(acc[r][1], ox1, oy1);
        unpack2(acc[r][2], ox2, oy2);
        unpack2(acc[r][3], ox3, oy3);
        __stcs(reinterpret_cast<float4*>(op),     make_float4(ox0, oy0, ox1, oy1));
        __stcs(reinterpret_cast<float4*>(op + 2), make_float4(ox2, oy2, ox3, oy3));
    }
}

// ---------------------------------------------------------------------------
// Kernel 2: bilinear sampling with zero padding — unchanged from the proven
// 66.5us version. One thread per pixel, 32 channels looped, corner indices
// clamped independently from raw coords (jnp semantics), validity folded
// into the weights.
// ---------------------------------------------------------------------------
__global__ __launch_bounds__(256) void sample_kernel(
    const float* __restrict__ x,
    float* __restrict__ out)
{
    const int px = blockIdx.x * 64 + threadIdx.x;
    const int py = blockIdx.y * 4 + threadIdx.y;
    const int b  = blockIdx.z;

    float2 off = __ldcs(&g_off_buf[b * Ss + py * Ww + px]);
    float ix = (float)px + off.x;
    float iy = (float)py + off.y;

    float x0f = floorf(ix);
    float y0f = floorf(iy);
    float wx1 = ix - x0f, wx0 = 1.0f - wx1;
    float wy1 = iy - y0f, wy0 = 1.0f - wy1;

    float fx0 = (x0f >= 0.0f && x0f <= 511.0f) ? 1.0f : 0.0f;
    float fx1 = (x0f >= -1.0f && x0f <= 510.0f) ? 1.0f : 0.0f;
    float fy0 = (y0f >= 0.0f && y0f <= 511.0f) ? 1.0f : 0.0f;
    float fy1 = (y0f >= -1.0f && y0f <= 510.0f) ? 1.0f : 0.0f;

    int ix0r = (int)x0f;
    int iy0r = (int)y0f;
    int xi0 = max(0, min(511, ix0r));
    int xi1 = max(0, min(511, ix0r + 1));
    int yi0 = max(0, min(511, iy0r));
    int yi1 = max(0, min(511, iy0r + 1));

    float w00 = wy0 * wx0 * (fy0 * fx0);
    float w01 = wy0 * wx1 * (fy0 * fx1);
    float w10 = wy1 * wx0 * (fy1 * fx0);
    float w11 = wy1 * wx1 * (fy1 * fx1);

    const int i00 = yi0 * Ww + xi0;
    const int i01 = yi0 * Ww + xi1;
    const int i10 = yi1 * Ww + xi0;
    const int i11 = yi1 * Ww + xi1;

    const float* xb = x + (size_t)b * Cc * Ss;
    size_t o = (size_t)b * Cc * Ss + (size_t)py * Ww + px;

#pragma unroll 4
    for (int c = 0; c < Cc; c++) {
        const float* p = xb + (size_t)c * Ss;
        float v = w00 * __ldg(p + i00)
                + w01 * __ldg(p + i01)
                + w10 * __ldg(p + i10)
                + w11 * __ldg(p + i11);
        __stcs(out + o + (size_t)c * Ss, v);
    }
}

extern "C" void kernel_launch(void* const* d_in, const int* in_sizes, int n_in,
                              void* d_out, int out_size)
{
    const float* x     = (const float*)d_in[0];  // (4, 32, 512, 512)
    const float* w_off = (const float*)d_in[1];  // (18, 32, 3, 3)
    const float* b_off = (const float*)d_in[2];  // (18,)
    float* out = (float*)d_out;                  // (4, 32, 512, 512)

    (void)in_sizes; (void)n_in; (void)out_size;

    dim3 g1(Ww / 128, Hh / 8, Bb);   // (4, 64, 4) = 1024 blocks of 64 threads
    conv_off_kernel<<<g1, 64>>>(x, w_off, b_off);

    dim3 g2(Ww / 64, Hh / 4, Bb);
    dim3 t2(64, 4);
    sample_kernel<<<g2, t2>>>(x, out);
}

// round 9
// speedup vs baseline: 1.5361x; 1.2485x over previous
#include <cuda_runtime.h>
#include <cstdint>

#define Hh 512
#define Ww 512
#define Cc 32
#define Bb 4
#define Ss (Hh*Ww)
#define NG 4               // channel groups
#define CPG (Cc/NG)        // 8 channels per group

// Partial per-pixel (off_x, off_y) per channel-group: 4 * 8MB = 32 MB scratch
__device__ float2 g_off_part[NG][Bb * Ss];

typedef unsigned long long ull;

__device__ __forceinline__ ull pack2(float a, float b) {
    ull r; asm("mov.b64 %0, {%1, %2};" : "=l"(r) : "f"(a), "f"(b)); return r;
}
__device__ __forceinline__ void unpack2(ull v, float& a, float& b) {
    asm("mov.b64 {%0, %1}, %2;" : "=f"(a), "=f"(b) : "l"(v));
}
__device__ __forceinline__ ull fma2(ull a, ull b, ull c) {
    ull d; asm("fma.rn.f32x2 %0, %1, %2, %3;" : "=l"(d) : "l"(a), "l"(b), "l"(c)); return d;
}

// ---------------------------------------------------------------------------
// Kernel 1 (R9): CHANNEL-SPLIT barrier-free offset conv.
// Evidence: 4 structurally different conv designs all sat at ~92-133us while
// per-pipe floors say ~25us. Common factor: a serial 32-channel chain per
// pixel-owning warp and only ~2k warps chip-wide. This version splits the
// channel loop over 4 blocks (grid.z = batch*4): serial chain /4, warps x4
// (8192 warps, ~56/SM). Each block accumulates 8 channels into a partial
// (off_x, off_y) buffer; the sampler sums the 4 partials.
// Warp strip = 128px x 4 rows; per channel stream 6 rows as aligned LDG.128
// + 2 edge scalars, rotate into 9-tap packed-f32x2 accumulation. No barriers.
// ---------------------------------------------------------------------------
__global__ __launch_bounds__(64) void conv_off_kernel(
    const float* __restrict__ x,
    const float* __restrict__ w_off,
    const float* __restrict__ b_off)
{
    __shared__ ull s_wk[CPG * 9];   // packed (w_ch0, w_ch1), this group's 8 ch

    const int tid  = threadIdx.x;
    const int wid  = tid >> 5;
    const int lane = tid & 31;

    const int grp = blockIdx.z & (NG - 1);
    const int bz  = blockIdx.z >> 2;          // batch
    const int c0  = grp * CPG;

    for (int i = tid; i < CPG * 9; i += 64)
        s_wk[i] = pack2(__ldg(w_off + c0 * 9 + i),
                        __ldg(w_off + 288 + c0 * 9 + i));
    __syncthreads();

    const int X0   = blockIdx.x * 128;
    const int ytop = blockIdx.y * 8 + wid * 4;   // out rows ytop..ytop+3
    const int cb   = X0 + 4 * lane;              // lane's first pixel column
    const float* xb = x + (size_t)bz * Cc * Ss;

    // bias only in group 0's partial
    const ull initp = (grp == 0) ? pack2(__ldg(b_off + 0), __ldg(b_off + 1))
                                 : pack2(0.0f, 0.0f);
    ull acc[4][4];
#pragma unroll
    for (int r = 0; r < 4; r++)
#pragma unroll
        for (int p = 0; p < 4; p++) acc[r][p] = initp;

    const bool has_left  = (cb > 0);
    const bool has_right = (cb + 4 < Ww);

#pragma unroll
    for (int c = 0; c < CPG; c++) {
        const float* xc = xb + (size_t)(c0 + c) * Ss;

        ull wk[9];
#pragma unroll
        for (int k = 0; k < 9; k++) wk[k] = s_wk[c * 9 + k];

#pragma unroll
        for (int j = 0; j < 6; j++) {           // input rows ytop-1 .. ytop+4
            int gy = ytop - 1 + j;
            float v0 = 0.f, v1 = 0.f, v2 = 0.f, v3 = 0.f, v4 = 0.f, v5 = 0.f;
            if ((unsigned)gy < (unsigned)Hh) {
                const float* rp = xc + gy * Ww + cb;
                float4 m = __ldg(reinterpret_cast<const float4*>(rp));
                v1 = m.x; v2 = m.y; v3 = m.z; v4 = m.w;
                if (has_left)  v0 = __ldg(rp - 1);
                if (has_right) v5 = __ldg(rp + 4);
            }
            ull pv[6];
            pv[0] = pack2(v0, v0); pv[1] = pack2(v1, v1);
            pv[2] = pack2(v2, v2); pv[3] = pack2(v3, v3);
            pv[4] = pack2(v4, v4); pv[5] = pack2(v5, v5);

            // input row gy feeds output row r = j - ky with weight row ky
#pragma unroll
            for (int ky = 0; ky < 3; ky++) {
                int r = j - ky;
                if (r >= 0 && r < 4) {          // compile-time (j,ky unrolled)
#pragma unroll
                    for (int p = 0; p < 4; p++) {
                        ull a = acc[r][p];
                        a = fma2(pv[p],     wk[ky * 3 + 0], a);
                        a = fma2(pv[p + 1], wk[ky * 3 + 1], a);
                        a = fma2(pv[p + 2], wk[ky * 3 + 2], a);
                        acc[r][p] = a;
                    }
                }
            }
        }
    }

    // store 4 rows x 4 px of partial (off_x, off_y): two STG.128 per row
#pragma unroll
    for (int r = 0; r < 4; r++) {
        int y = ytop + r;
        float2* op = g_off_part[grp] + (size_t)bz * Ss + (size_t)y * Ww + cb;
        float ox0, oy0, ox1, oy1, ox2, oy2, ox3, oy3;
        unpack2(acc[r][0], ox0, oy0);
        unpack2(acc[r][1], ox1, oy1);
        unpack2(acc[r][2], ox2, oy2);
        unpack2(acc[r][3], ox3, oy3);
        __stcs(reinterpret_cast<float4*>(op),     make_float4(ox0, oy0, ox1, oy1));
        __stcs(reinterpret_cast<float4*>(op + 2), make_float4(ox2, oy2, ox3, oy3));
    }
}

// ---------------------------------------------------------------------------
// Kernel 2: bilinear sampling (proven 66.5us path) — now sums the 4 partial
// offsets first. Corner indices clamped independently from raw coords (jnp
// semantics), validity folded into weights, coalesced channel loop.
// ---------------------------------------------------------------------------
__global__ __launch_bounds__(256) void sample_kernel(
    const float* __restrict__ x,
    float* __restrict__ out)
{
    const int px = blockIdx.x * 64 + threadIdx.x;
    const int py = blockIdx.y * 4 + threadIdx.y;
    const int b  = blockIdx.z;

    const size_t oidx = (size_t)b * Ss + (size_t)py * Ww + px;
    float2 p0 = __ldcs(&g_off_part[0][oidx]);
    float2 p1 = __ldcs(&g_off_part[1][oidx]);
    float2 p2 = __ldcs(&g_off_part[2][oidx]);
    float2 p3 = __ldcs(&g_off_part[3][oidx]);
    float offx = (p0.x + p1.x) + (p2.x + p3.x);
    float offy = (p0.y + p1.y) + (p2.y + p3.y);

    float ix = (float)px + offx;
    float iy = (float)py + offy;

    float x0f = floorf(ix);
    float y0f = floorf(iy);
    float wx1 = ix - x0f, wx0 = 1.0f - wx1;
    float wy1 = iy - y0f, wy0 = 1.0f - wy1;

    float fx0 = (x0f >= 0.0f && x0f <= 511.0f) ? 1.0f : 0.0f;
    float fx1 = (x0f >= -1.0f && x0f <= 510.0f) ? 1.0f : 0.0f;
    float fy0 = (y0f >= 0.0f && y0f <= 511.0f) ? 1.0f : 0.0f;
    float fy1 = (y0f >= -1.0f && y0f <= 510.0f) ? 1.0f : 0.0f;

    int ix0r = (int)x0f;
    int iy0r = (int)y0f;
    int xi0 = max(0, min(511, ix0r));
    int xi1 = max(0, min(511, ix0r + 1));
    int yi0 = max(0, min(511, iy0r));
    int yi1 = max(0, min(511, iy0r + 1));

    float w00 = wy0 * wx0 * (fy0 * fx0);
    float w01 = wy0 * wx1 * (fy0 * fx1);
    float w10 = wy1 * wx0 * (fy1 * fx0);
    float w11 = wy1 * wx1 * (fy1 * fx1);

    const int i00 = yi0 * Ww + xi0;
    const int i01 = yi0 * Ww + xi1;
    const int i10 = yi1 * Ww + xi0;
    const int i11 = yi1 * Ww + xi1;

    const float* xb = x + (size_t)b * Cc * Ss;
    size_t o = (size_t)b * Cc * Ss + (size_t)py * Ww + px;

#pragma unroll 4
    for (int c = 0; c < Cc; c++) {
        const float* p = xb + (size_t)c * Ss;
        float v = w00 * __ldg(p + i00)
                + w01 * __ldg(p + i01)
                + w10 * __ldg(p + i10)
                + w11 * __ldg(p + i11);
        __stcs(out + o + (size_t)c * Ss, v);
    }
}

// Alignment no-ops: pad the per-call launch count to 5 so that executed
// launch #6 (the one ncu -s 5 -c 1 captures) is the CONV kernel of the
// second call — finally getting conv counters instead of the sampler's.
__global__ void noop_kernel() {}

extern "C" void kernel_launch(void* const* d_in, const int* in_sizes, int n_in,
                              void* d_out, int out_size)
{
    const float* x     = (const float*)d_in[0];  // (4, 32, 512, 512)
    const float* w_off = (const float*)d_in[1];  // (18, 32, 3, 3)
    const float* b_off = (const float*)d_in[2];  // (18,)
    float* out = (float*)d_out;                  // (4, 32, 512, 512)

    (void)in_sizes; (void)n_in; (void)out_size;

    dim3 g1(Ww / 128, Hh / 8, Bb * NG);   // (4, 64, 16) = 4096 blocks x 64 thr
    conv_off_kernel<<<g1, 64>>>(x, w_off, b_off);

    dim3 g2(Ww / 64, Hh / 4, Bb);
    dim3 t2(64, 4);
    sample_kernel<<<g2, t2>>>(x, out);

    noop_kernel<<<1, 32>>>();
    noop_kernel<<<1, 32>>>();
    noop_kernel<<<1, 32>>>();
}